// round 16
// baseline (speedup 1.0000x reference)
#include <cuda_runtime.h>
#include <cstdint>

// Problem constants
#define B_ 4
#define C_ 64
#define H_ 128
#define W_ 128
#define HW_ 16384
#define OCH_ 18
#define COUT_ 64
#define K2_ 9

#define VP 68   // V tile row pitch (words) — conflict-free A-frag LDS

// Scratch (device globals)
__device__ float g_offs[B_ * OCH_ * HW_];        // offset conv result
__device__ float g_xt[B_ * HW_ * C_];            // x transposed+tf32: [b][h][w][c]
__device__ uint32_t g_wt[K2_ * C_ * COUT_];      // w_deform tf32 PAIR-PACKED
__device__ uint32_t g_wo[3 * 96 * 56];           // w_offset tf32 PAIR-PACKED (pitch 56)

// ---- packed f32x2 helpers ----
__device__ __forceinline__ unsigned long long pk2(float a, float b) {
    unsigned long long r;
    asm("mov.b64 %0, {%1, %2};" : "=l"(r) : "f"(a), "f"(b));
    return r;
}
__device__ __forceinline__ unsigned long long fma2(unsigned long long a,
                                                   unsigned long long b,
                                                   unsigned long long c) {
    unsigned long long d;
    asm("fma.rn.f32x2 %0, %1, %2, %3;" : "=l"(d) : "l"(a), "l"(b), "l"(c));
    return d;
}
__device__ __forceinline__ float2 upk(unsigned long long a) {
    float2 f;
    asm("mov.b64 {%0, %1}, %2;" : "=f"(f.x), "=f"(f.y) : "l"(a));
    return f;
}
__device__ __forceinline__ uint32_t to_tf32(float f) {
    uint32_t r;
    asm("cvt.rna.tf32.f32 %0, %1;" : "=r"(r) : "f"(f));
    return r;
}

// warp-level tf32 MMA: D(16x8) += A(16x8) * B(8x8)
__device__ __forceinline__ void mma_tf32(float* d, uint32_t a0, uint32_t a1,
                                         uint32_t a2, uint32_t a3,
                                         uint32_t b0, uint32_t b1) {
    asm volatile(
        "mma.sync.aligned.m16n8k8.row.col.f32.tf32.tf32.f32 "
        "{%0,%1,%2,%3}, {%4,%5,%6,%7}, {%8,%9}, {%0,%1,%2,%3};"
        : "+f"(d[0]), "+f"(d[1]), "+f"(d[2]), "+f"(d[3])
        : "r"(a0), "r"(a1), "r"(a2), "r"(a3), "r"(b0), "r"(b1));
}

// ---------------------------------------------------------------------------
// Fused prep kernel (R13/R14 proven):
//   blocks [0,512)    : transpose x -> g_xt[b][h][w][c], tf32-rounded
//   blocks [512,656)  : w_deform -> g_wt pair-packed tf32
//   blocks [656,710)  : w_offset -> g_wo pair-packed tf32 (pitch 56)
// ---------------------------------------------------------------------------
__global__ __launch_bounds__(256) void k_prep(
    const float* __restrict__ x, const float* __restrict__ wd,
    const float* __restrict__ wo) {
    __shared__ float tile[64 * 129];
    int bid = blockIdx.x;
    int t = threadIdx.x;

    if (bid < 512) {
        int b = bid >> 7, h = bid & 127;
        const float* xb = x + ((size_t)b * C_ * H_ + h) * W_;
#pragma unroll
        for (int i = 0; i < 32; ++i) {
            int e = t + i * 256;
            int c = e >> 7, w = e & 127;
            tile[c * 129 + w] = xb[(size_t)c * HW_ + w];
        }
        __syncthreads();
        uint32_t* ob = (uint32_t*)(g_xt + ((size_t)b * H_ + h) * W_ * C_);
#pragma unroll
        for (int i = 0; i < 32; ++i) {
            int e = t + i * 256;
            int w = e >> 6, c = e & 63;
            ob[w * C_ + c] = to_tf32(tile[c * 129 + w]);
        }
    } else if (bid < 656) {
        int idx = (bid - 512) * 256 + t;
        if (idx < K2_ * C_ * COUT_) {
            int tap = idx >> 12;
            int r   = idx & 4095;
            int c   = r >> 6;
            int o   = r & 63;
            int R    = ((c >> 3) << 2) + (c & 3);
            int slot = (c >> 2) & 1;
            g_wt[tap * 4096 + R * 128 + o * 2 + slot] =
                to_tf32(wd[(o * C_ + c) * K2_ + tap]);
        }
    } else {
        int idx = (bid - 656) * 256 + t;
        if (idx < 3 * 192 * 24) {
            int ky = idx / (192 * 24);
            int r  = idx % (192 * 24);
            int k  = r / 24;
            int n  = r % 24;
            int kx = k >> 6;
            int c  = k & 63;
            float v = (n < OCH_) ? wo[((size_t)n * C_ + c) * K2_ + ky * 3 + kx] : 0.f;
            int ksg  = (kx << 3) + (c >> 3);
            int tgl  = c & 3;
            int slot = (c >> 2) & 1;
            g_wo[ky * 5376 + (ksg * 4 + tgl) * 56 + n * 2 + slot] = to_tf32(v);
        }
    }
}

// ---------------------------------------------------------------------------
// Offset conv as tf32 mma (R14 proven): one (b,h) row per block.
// ---------------------------------------------------------------------------
#define XSP 68
#define OSM_WORDS (130 * XSP + 5376)
__global__ __launch_bounds__(256) void k_offset_mma() {
    extern __shared__ uint32_t osm[];
    uint32_t* xs  = osm;             // [130][XSP]
    uint32_t* wos = osm + 130 * XSP; // [96][56] pair-packed

    int bh = blockIdx.x;
    int b = bh >> 7, h = bh & 127;
    int t = threadIdx.x;
    int wid = t >> 5, lane = t & 31;
    int g  = lane >> 2;
    int tg = lane & 3;
    int warp_m = wid * 16;

    const uint32_t* xt = (const uint32_t*)(g_xt + (size_t)b * HW_ * C_);

    float acc[3][4];
#pragma unroll
    for (int i = 0; i < 3; ++i)
#pragma unroll
        for (int j = 0; j < 4; ++j) acc[i][j] = 0.f;

    for (int ky = 0; ky < 3; ++ky) {
        int y = h - 1 + ky;
        bool yv = (y >= 0) && (y < H_);

        for (int idx = t; idx < 130 * 16; idx += 256) {
            int j = idx >> 4, q = (idx & 15) << 2;
            uint4 v = make_uint4(0u, 0u, 0u, 0u);
            if (yv && j >= 1 && j <= 128)
                v = *(const uint4*)(xt + ((size_t)y * W_ + (j - 1)) * C_ + q);
            *(uint4*)(xs + j * XSP + q) = v;
        }
        {
            const uint4* ws4 = (const uint4*)(g_wo + ky * 5376);
            for (int idx = t; idx < 1344; idx += 256)
                ((uint4*)wos)[idx] = ws4[idx];
        }
        __syncthreads();

#pragma unroll
        for (int ks = 0; ks < 24; ++ks) {
            int k0 = ks * 8;
            int kx = k0 >> 6;
            int c0 = k0 & 63;
            uint32_t a0 = xs[(warp_m + g + kx)     * XSP + c0 + tg];
            uint32_t a1 = xs[(warp_m + g + 8 + kx) * XSP + c0 + tg];
            uint32_t a2 = xs[(warp_m + g + kx)     * XSP + c0 + tg + 4];
            uint32_t a3 = xs[(warp_m + g + 8 + kx) * XSP + c0 + tg + 4];
            const uint32_t* wp2 = wos + (ks * 4 + tg) * 56 + g * 2;
#pragma unroll
            for (int nb = 0; nb < 3; ++nb) {
                uint2 bp = *(const uint2*)(wp2 + nb * 16);
                mma_tf32(acc[nb], a0, a1, a2, a3, bp.x, bp.y);
            }
        }
        __syncthreads();
    }

    int p = warp_m + g;
    float* ofb = g_offs + ((size_t)b * OCH_ * H_ + h) * W_;
#pragma unroll
    for (int nb = 0; nb < 3; ++nb) {
        int och = nb * 8 + tg * 2;
        if (och < OCH_) {
            ofb[(size_t)och * HW_ + p]     = acc[nb][0];
            ofb[(size_t)och * HW_ + p + 8] = acc[nb][2];
        }
        if (och + 1 < OCH_) {
            ofb[(size_t)(och + 1) * HW_ + p]     = acc[nb][1];
            ofb[(size_t)(och + 1) * HW_ + p + 8] = acc[nb][3];
        }
    }
}

// ---------------------------------------------------------------------------
// Main deform-conv: tf32 mma, single-barrier pipeline, M32xN32 warp tile,
// tap double-buffered V. NEW: B-fragments loaded DIRECTLY from global g_wt
// (pair-packed = fragment layout; W tile is L2/L1-hot). W smem buffers
// removed -> smem 77,824B -> 3 blocks/SM with barrier count unchanged.
// ---------------------------------------------------------------------------
#define VW 8704                 // V buffer words (128*68)
#define PW_OFF (2 * VW)         // 17408
#define PI_OFF (PW_OFF + 2 * 128 * 4)   // 18432
#define DSM_WORDS (PI_OFF + 2 * 128 * 4)  // 19456
#define DSM_BYTES (DSM_WORDS * 4)         // 77824

__global__ __launch_bounds__(256, 3) void k_deform_mma(float* __restrict__ out) {
    extern __shared__ uint32_t dsm[];
    float4* pwb = (float4*)(dsm + PW_OFF);
    int4*   pib = (int4*)(dsm + PI_OFF);

    int bh = blockIdx.x;
    int b = bh >> 7, h = bh & 127;
    int t = threadIdx.x;
    int wid = t >> 5, lane = t & 31;
    int g  = lane >> 2;
    int tg = lane & 3;
    int warp_m = (wid & 3) * 32;   // pixel slab (M32)
    int warp_n = (wid >> 2) * 32;  // o half (N32)

    int half = lane >> 4;          // gather: pixel select within warp pair
    int cs   = (lane & 15) << 2;   // channel segment (4 floats)

    const float* ob = g_offs + ((size_t)b * OCH_ * H_ + h) * W_;
    const float* xt = g_xt + (size_t)b * HW_ * C_;

    float acc[2][4][4];
#pragma unroll
    for (int m = 0; m < 2; ++m)
#pragma unroll
        for (int i = 0; i < 4; ++i)
#pragma unroll
            for (int j = 0; j < 4; ++j) acc[m][i][j] = 0.f;

    // ---- params(0) prologue ----
    if (t < 128) {
        int px = t;
        float dy = ob[0 * HW_ + px];
        float dx = ob[1 * HW_ + px];
        float py = (float)(h - 1) + dy;
        float pxf = (float)(px - 1) + dx;
        float y0f = floorf(py), x0f = floorf(pxf);
        float ly = py - y0f, lx = pxf - x0f;
        int y0 = (int)y0f, x0 = (int)x0f;
        int y1 = y0 + 1,   x1 = x0 + 1;
        bool vy0 = (y0 >= 0) && (y0 < H_), vy1 = (y1 >= 0) && (y1 < H_);
        bool vx0 = (x0 >= 0) && (x0 < W_), vx1 = (x1 >= 0) && (x1 < W_);
        float4 wg;
        wg.x = (1.f - ly) * (1.f - lx) * ((vy0 && vx0) ? 1.f : 0.f);
        wg.y = (1.f - ly) * lx         * ((vy0 && vx1) ? 1.f : 0.f);
        wg.z = ly * (1.f - lx)         * ((vy1 && vx0) ? 1.f : 0.f);
        wg.w = ly * lx                 * ((vy1 && vx1) ? 1.f : 0.f);
        int y0c = min(max(y0, 0), H_ - 1), y1c = min(max(y1, 0), H_ - 1);
        int x0c = min(max(x0, 0), W_ - 1), x1c = min(max(x1, 0), W_ - 1);
        int4 ix;
        ix.x = y0c * W_ + x0c; ix.y = y0c * W_ + x1c;
        ix.z = y1c * W_ + x0c; ix.w = y1c * W_ + x1c;
        pwb[px] = wg;
        pib[px] = ix;
    }
    __syncthreads();

    for (int it = 0; it < 10; ++it) {
        int cur = it & 1, prv = cur ^ 1;
        uint32_t* vcur = dsm + cur * VW;
        uint32_t* vprv = dsm + prv * VW;

        if (it < 9) {
            // params(it+1) into prv param buffer
            if (it < 8 && t < 128) {
                int tap = it + 1;
                int ky = tap / 3, kx = tap % 3;
                int px = t;
                float dy = ob[(size_t)(2 * tap)     * HW_ + px];
                float dx = ob[(size_t)(2 * tap + 1) * HW_ + px];
                float py = (float)(h - 1 + ky) + dy;
                float pxf = (float)(px - 1 + kx) + dx;
                float y0f = floorf(py), x0f = floorf(pxf);
                float ly = py - y0f, lx = pxf - x0f;
                int y0 = (int)y0f, x0 = (int)x0f;
                int y1 = y0 + 1,   x1 = x0 + 1;
                bool vy0 = (y0 >= 0) && (y0 < H_), vy1 = (y1 >= 0) && (y1 < H_);
                bool vx0 = (x0 >= 0) && (x0 < W_), vx1 = (x1 >= 0) && (x1 < W_);
                float4 wg;
                wg.x = (1.f - ly) * (1.f - lx) * ((vy0 && vx0) ? 1.f : 0.f);
                wg.y = (1.f - ly) * lx         * ((vy0 && vx1) ? 1.f : 0.f);
                wg.z = ly * (1.f - lx)         * ((vy1 && vx0) ? 1.f : 0.f);
                wg.w = ly * lx                 * ((vy1 && vx1) ? 1.f : 0.f);
                int y0c = min(max(y0, 0), H_ - 1), y1c = min(max(y1, 0), H_ - 1);
                int x0c = min(max(x0, 0), W_ - 1), x1c = min(max(x1, 0), W_ - 1);
                int4 ix;
                ix.x = y0c * W_ + x0c; ix.y = y0c * W_ + x1c;
                ix.z = y1c * W_ + x0c; ix.w = y1c * W_ + x1c;
                pwb[prv * 128 + px] = wg;
                pib[prv * 128 + px] = ix;
            }
        }

        // B-fragment global base for tap (it-1)
        const uint32_t* wgl = g_wt + (it - 1) * 4096 + tg * 128 + warp_n * 2 + g * 2;

        // ---- interleaved gather(it) + mma(it-1) ----
#pragma unroll
        for (int i = 0; i < 8; ++i) {
            if (it < 9) {
                int px = i * 16 + (wid << 1) + half;
                float4 wg = pwb[cur * 128 + px];
                int4   ix = pib[cur * 128 + px];
                ulonglong2 a4 = *(const ulonglong2*)(xt + (size_t)ix.x * C_ + cs);
                ulonglong2 b4 = *(const ulonglong2*)(xt + (size_t)ix.y * C_ + cs);
                ulonglong2 c4 = *(const ulonglong2*)(xt + (size_t)ix.z * C_ + cs);
                ulonglong2 d4 = *(const ulonglong2*)(xt + (size_t)ix.w * C_ + cs);
                unsigned long long w00p = pk2(wg.x, wg.x);
                unsigned long long w01p = pk2(wg.y, wg.y);
                unsigned long long w10p = pk2(wg.z, wg.z);
                unsigned long long w11p = pk2(wg.w, wg.w);
                unsigned long long lo = fma2(w00p, a4.x,
                                        fma2(w01p, b4.x,
                                        fma2(w10p, c4.x,
                                        fma2(w11p, d4.x, 0ULL))));
                unsigned long long hi = fma2(w00p, a4.y,
                                        fma2(w01p, b4.y,
                                        fma2(w10p, c4.y,
                                        fma2(w11p, d4.y, 0ULL))));
                float2 flo = upk(lo), fhi = upk(hi);
                uint4 u;
                u.x = to_tf32(flo.x); u.y = to_tf32(flo.y);
                u.z = to_tf32(fhi.x); u.w = to_tf32(fhi.y);
                *(uint4*)(vcur + px * VP + cs) = u;
            }
            if (it > 0) {
                int k0 = i * 8;
                uint32_t a[2][4];
#pragma unroll
                for (int mt = 0; mt < 2; ++mt) {
                    int row = warp_m + mt * 16;
                    a[mt][0] = vprv[(row + g)     * VP + k0 + tg];
                    a[mt][1] = vprv[(row + g + 8) * VP + k0 + tg];
                    a[mt][2] = vprv[(row + g)     * VP + k0 + tg + 4];
                    a[mt][3] = vprv[(row + g + 8) * VP + k0 + tg + 4];
                }
                const uint32_t* wp2 = wgl + i * 512;   // (i*4)*128 words
#pragma unroll
                for (int nb = 0; nb < 4; ++nb) {
                    uint2 bp = *(const uint2*)(wp2 + nb * 16);
#pragma unroll
                    for (int mt = 0; mt < 2; ++mt)
                        mma_tf32(acc[mt][nb], a[mt][0], a[mt][1], a[mt][2],
                                 a[mt][3], bp.x, bp.y);
                }
            }
        }
        __syncthreads();
    }

    // ---- epilogue: smem-transposed coalesced stores ----
    {
        uint32_t* outs = dsm;   // reuse: 64*132 = 8448 words
#pragma unroll
        for (int mt = 0; mt < 2; ++mt) {
            int p = warp_m + mt * 16 + g;
#pragma unroll
            for (int nb = 0; nb < 4; ++nb) {
                int o = warp_n + nb * 8 + tg * 2;
                outs[o       * 132 + p]     = __float_as_uint(acc[mt][nb][0]);
                outs[(o + 1) * 132 + p]     = __float_as_uint(acc[mt][nb][1]);
                outs[o       * 132 + p + 8] = __float_as_uint(acc[mt][nb][2]);
                outs[(o + 1) * 132 + p + 8] = __float_as_uint(acc[mt][nb][3]);
            }
        }
        __syncthreads();
        float* outb = out + ((size_t)b * COUT_ * H_ + h) * W_;
#pragma unroll
        for (int i = 0; i < 8; ++i) {
            int e = t + i * 256;
            int o = e >> 5, q = (e & 31) << 2;
            uint4 v = *(uint4*)(outs + o * 132 + q);
            *(uint4*)(outb + (size_t)o * HW_ + q) = v;
        }
    }
}

// ---------------------------------------------------------------------------
extern "C" void kernel_launch(void* const* d_in, const int* in_sizes, int n_in,
                              void* d_out, int out_size) {
    const float* x        = (const float*)d_in[0];
    const float* w_offset = (const float*)d_in[1];
    const float* w_deform = (const float*)d_in[2];
    float* out = (float*)d_out;

    cudaFuncSetAttribute(k_deform_mma,
                         cudaFuncAttributeMaxDynamicSharedMemorySize, DSM_BYTES);
    cudaFuncSetAttribute(k_offset_mma,
                         cudaFuncAttributeMaxDynamicSharedMemorySize, OSM_WORDS * 4);

    k_prep<<<710, 256>>>(x, w_deform, w_offset);
    k_offset_mma<<<B_ * H_, 256, OSM_WORDS * 4>>>();
    k_deform_mma<<<B_ * H_, 256, DSM_BYTES>>>(out);
}

// round 17
// speedup vs baseline: 1.2116x; 1.2116x over previous
#include <cuda_runtime.h>
#include <cstdint>

// Problem constants
#define B_ 4
#define C_ 64
#define H_ 128
#define W_ 128
#define HW_ 16384
#define OCH_ 18
#define COUT_ 64
#define K2_ 9

#define VP 68   // V tile row pitch (words) — conflict-free A-frag LDS

// Scratch (device globals)
__device__ float g_offs[B_ * OCH_ * HW_];        // offset conv result
__device__ float g_xt[B_ * HW_ * C_];            // x transposed+tf32: [b][h][w][c]
__device__ uint32_t g_wt[K2_ * C_ * COUT_];      // w_deform tf32 PAIR-PACKED
__device__ uint32_t g_wo[3 * 192 * 24];          // w_offset tf32: [ky][kx*64+c][och24]

// ---- packed f32x2 helpers ----
__device__ __forceinline__ unsigned long long pk2(float a, float b) {
    unsigned long long r;
    asm("mov.b64 %0, {%1, %2};" : "=l"(r) : "f"(a), "f"(b));
    return r;
}
__device__ __forceinline__ unsigned long long fma2(unsigned long long a,
                                                   unsigned long long b,
                                                   unsigned long long c) {
    unsigned long long d;
    asm("fma.rn.f32x2 %0, %1, %2, %3;" : "=l"(d) : "l"(a), "l"(b), "l"(c));
    return d;
}
__device__ __forceinline__ float2 upk(unsigned long long a) {
    float2 f;
    asm("mov.b64 {%0, %1}, %2;" : "=f"(f.x), "=f"(f.y) : "l"(a));
    return f;
}
__device__ __forceinline__ uint32_t to_tf32(float f) {
    uint32_t r;
    asm("cvt.rna.tf32.f32 %0, %1;" : "=r"(r) : "f"(f));
    return r;
}

// warp-level tf32 MMA: D(16x8) += A(16x8) * B(8x8)
__device__ __forceinline__ void mma_tf32(float* d, uint32_t a0, uint32_t a1,
                                         uint32_t a2, uint32_t a3,
                                         uint32_t b0, uint32_t b1) {
    asm volatile(
        "mma.sync.aligned.m16n8k8.row.col.f32.tf32.tf32.f32 "
        "{%0,%1,%2,%3}, {%4,%5,%6,%7}, {%8,%9}, {%0,%1,%2,%3};"
        : "+f"(d[0]), "+f"(d[1]), "+f"(d[2]), "+f"(d[3])
        : "r"(a0), "r"(a1), "r"(a2), "r"(a3), "r"(b0), "r"(b1));
}

// ---------------------------------------------------------------------------
// Fused prep kernel:
//   blocks [0,512)    : transpose x -> g_xt (tf32). Loads now LDG.128.
//   blocks [512,656)  : w_deform -> g_wt pair-packed tf32
//   blocks [656,710)  : w_offset -> g_wo[ky][kx*64+c][och24] tf32
// ---------------------------------------------------------------------------
__global__ __launch_bounds__(256) void k_prep(
    const float* __restrict__ x, const float* __restrict__ wd,
    const float* __restrict__ wo) {
    __shared__ float tile[64 * 129];
    int bid = blockIdx.x;
    int t = threadIdx.x;

    if (bid < 512) {
        int b = bid >> 7, h = bid & 127;
        const float* xb = x + ((size_t)b * C_ * H_ + h) * W_;
        // vectorized loads: 8 x LDG.128 per thread (w stays coalesced)
#pragma unroll
        for (int i = 0; i < 8; ++i) {
            int e = t + i * 256;          // 2048 float4 elements
            int c = e >> 5;               // 32 float4 per row
            int w4 = (e & 31) << 2;
            float4 v = *(const float4*)(xb + (size_t)c * HW_ + w4);
            float* dst = tile + c * 129 + w4;
            dst[0] = v.x; dst[1] = v.y; dst[2] = v.z; dst[3] = v.w;
        }
        __syncthreads();
        uint32_t* ob = (uint32_t*)(g_xt + ((size_t)b * H_ + h) * W_ * C_);
#pragma unroll
        for (int i = 0; i < 32; ++i) {
            int e = t + i * 256;
            int w = e >> 6, c = e & 63;
            ob[w * C_ + c] = to_tf32(tile[c * 129 + w]);
        }
    } else if (bid < 656) {
        int idx = (bid - 512) * 256 + t;
        if (idx < K2_ * C_ * COUT_) {
            int tap = idx >> 12;
            int r   = idx & 4095;
            int c   = r >> 6;
            int o   = r & 63;
            int R    = ((c >> 3) << 2) + (c & 3);
            int slot = (c >> 2) & 1;
            g_wt[tap * 4096 + R * 128 + o * 2 + slot] =
                to_tf32(wd[(o * C_ + c) * K2_ + tap]);
        }
    } else {
        int idx = (bid - 656) * 256 + t;
        if (idx < 3 * 192 * 24) {
            int ky = idx / (192 * 24);
            int r  = idx % (192 * 24);
            int k  = r / 24;
            int n  = r % 24;
            int kx = k >> 6;
            int c  = k & 63;
            float v = (n < OCH_) ? wo[((size_t)n * C_ + c) * K2_ + ky * 3 + kx] : 0.f;
            g_wo[idx] = to_tf32(v);
        }
    }
}

// ---------------------------------------------------------------------------
// Offset conv as tf32 mma (R9/R13 proven config): one (b,h) row per block.
// ---------------------------------------------------------------------------
#define XSP 68
#define OSM_WORDS (130 * XSP + 192 * 24)
__global__ __launch_bounds__(256) void k_offset_mma() {
    extern __shared__ uint32_t osm[];
    uint32_t* xs  = osm;             // [130][XSP]
    uint32_t* wos = osm + 130 * XSP; // [192][24]

    int bh = blockIdx.x;
    int b = bh >> 7, h = bh & 127;
    int t = threadIdx.x;
    int wid = t >> 5, lane = t & 31;
    int g  = lane >> 2;
    int tg = lane & 3;
    int warp_m = wid * 16;

    const uint32_t* xt = (const uint32_t*)(g_xt + (size_t)b * HW_ * C_);

    float acc[3][4];
#pragma unroll
    for (int i = 0; i < 3; ++i)
#pragma unroll
        for (int j = 0; j < 4; ++j) acc[i][j] = 0.f;

    for (int ky = 0; ky < 3; ++ky) {
        int y = h - 1 + ky;
        bool yv = (y >= 0) && (y < H_);

        for (int idx = t; idx < 130 * 16; idx += 256) {
            int j = idx >> 4, q = (idx & 15) << 2;
            uint4 v = make_uint4(0u, 0u, 0u, 0u);
            if (yv && j >= 1 && j <= 128)
                v = *(const uint4*)(xt + ((size_t)y * W_ + (j - 1)) * C_ + q);
            *(uint4*)(xs + j * XSP + q) = v;
        }
        {
            const uint4* ws4 = (const uint4*)(g_wo + ky * 4608);
            for (int idx = t; idx < 1152; idx += 256)
                ((uint4*)wos)[idx] = ws4[idx];
        }
        __syncthreads();

#pragma unroll
        for (int ks = 0; ks < 24; ++ks) {
            int k0 = ks * 8;
            int kx = k0 >> 6;
            int c0 = k0 & 63;
            uint32_t a0 = xs[(warp_m + g + kx)     * XSP + c0 + tg];
            uint32_t a1 = xs[(warp_m + g + 8 + kx) * XSP + c0 + tg];
            uint32_t a2 = xs[(warp_m + g + kx)     * XSP + c0 + tg + 4];
            uint32_t a3 = xs[(warp_m + g + 8 + kx) * XSP + c0 + tg + 4];
#pragma unroll
            for (int nb = 0; nb < 3; ++nb) {
                uint32_t b0 = wos[(k0 + tg)     * 24 + nb * 8 + g];
                uint32_t b1 = wos[(k0 + tg + 4) * 24 + nb * 8 + g];
                mma_tf32(acc[nb], a0, a1, a2, a3, b0, b1);
            }
        }
        __syncthreads();
    }

    int p = warp_m + g;
    float* ofb = g_offs + ((size_t)b * OCH_ * H_ + h) * W_;
#pragma unroll
    for (int nb = 0; nb < 3; ++nb) {
        int och = nb * 8 + tg * 2;
        if (och < OCH_) {
            ofb[(size_t)och * HW_ + p]     = acc[nb][0];
            ofb[(size_t)och * HW_ + p + 8] = acc[nb][2];
        }
        if (och + 1 < OCH_) {
            ofb[(size_t)(och + 1) * HW_ + p]     = acc[nb][1];
            ofb[(size_t)(och + 1) * HW_ + p + 8] = acc[nb][3];
        }
    }
}

// ---------------------------------------------------------------------------
// Main deform-conv (R13 measured-best config, byte-identical): tf32 mma,
// single-barrier pipeline, pair-packed W staged in smem, tap double
// buffering, M32xN32 warp tile, smem-transposed coalesced epilogue.
// ---------------------------------------------------------------------------
#define VW 8704                 // V buffer words (128*68)
#define WW 4608                 // W buffer words (32 rows * 136 pitch, padded)
#define PW_OFF (2 * VW + 2 * WW)
#define PI_OFF (PW_OFF + 2 * 128 * 4)
#define DSM_WORDS (PI_OFF + 2 * 128 * 4)
#define DSM_BYTES (DSM_WORDS * 4)

__global__ __launch_bounds__(256, 2) void k_deform_mma(float* __restrict__ out) {
    extern __shared__ uint32_t dsm[];
    float4* pwb = (float4*)(dsm + PW_OFF);
    int4*   pib = (int4*)(dsm + PI_OFF);

    int bh = blockIdx.x;
    int b = bh >> 7, h = bh & 127;
    int t = threadIdx.x;
    int wid = t >> 5, lane = t & 31;
    int g  = lane >> 2;
    int tg = lane & 3;
    int warp_m = (wid & 3) * 32;   // pixel slab (M32)
    int warp_n = (wid >> 2) * 32;  // o half (N32)

    int half = lane >> 4;          // gather: pixel select within warp pair
    int cs   = (lane & 15) << 2;   // channel segment (4 floats)

    const float* ob = g_offs + ((size_t)b * OCH_ * H_ + h) * W_;
    const float* xt = g_xt + (size_t)b * HW_ * C_;

    float acc[2][4][4];
#pragma unroll
    for (int m = 0; m < 2; ++m)
#pragma unroll
        for (int i = 0; i < 4; ++i)
#pragma unroll
            for (int j = 0; j < 4; ++j) acc[m][i][j] = 0.f;

    // ---- params(0) prologue ----
    if (t < 128) {
        int px = t;
        float dy = ob[0 * HW_ + px];
        float dx = ob[1 * HW_ + px];
        float py = (float)(h - 1) + dy;
        float pxf = (float)(px - 1) + dx;
        float y0f = floorf(py), x0f = floorf(pxf);
        float ly = py - y0f, lx = pxf - x0f;
        int y0 = (int)y0f, x0 = (int)x0f;
        int y1 = y0 + 1,   x1 = x0 + 1;
        bool vy0 = (y0 >= 0) && (y0 < H_), vy1 = (y1 >= 0) && (y1 < H_);
        bool vx0 = (x0 >= 0) && (x0 < W_), vx1 = (x1 >= 0) && (x1 < W_);
        float4 wg;
        wg.x = (1.f - ly) * (1.f - lx) * ((vy0 && vx0) ? 1.f : 0.f);
        wg.y = (1.f - ly) * lx         * ((vy0 && vx1) ? 1.f : 0.f);
        wg.z = ly * (1.f - lx)         * ((vy1 && vx0) ? 1.f : 0.f);
        wg.w = ly * lx                 * ((vy1 && vx1) ? 1.f : 0.f);
        int y0c = min(max(y0, 0), H_ - 1), y1c = min(max(y1, 0), H_ - 1);
        int x0c = min(max(x0, 0), W_ - 1), x1c = min(max(x1, 0), W_ - 1);
        int4 ix;
        ix.x = y0c * W_ + x0c; ix.y = y0c * W_ + x1c;
        ix.z = y1c * W_ + x0c; ix.w = y1c * W_ + x1c;
        pwb[px] = wg;
        pib[px] = ix;
    }
    __syncthreads();

    for (int it = 0; it < 10; ++it) {
        int cur = it & 1, prv = cur ^ 1;
        uint32_t* vcur = dsm + cur * VW;
        uint32_t* vprv = dsm + prv * VW;
        uint32_t* wcur = dsm + 2 * VW + cur * WW;
        uint32_t* wprv = dsm + 2 * VW + prv * WW;

        if (it < 9) {
            // stage W(it): vectorized copy of pre-packed tile
            const uint4* src = (const uint4*)(g_wt + it * 4096);
#pragma unroll
            for (int i = t; i < 1024; i += 256) {
                int R = i >> 5;
                int col = (i & 31) << 2;
                *(uint4*)(wcur + R * 136 + col) = src[i];
            }
            // params(it+1) into prv param buffer
            if (it < 8 && t < 128) {
                int tap = it + 1;
                int ky = tap / 3, kx = tap % 3;
                int px = t;
                float dy = ob[(size_t)(2 * tap)     * HW_ + px];
                float dx = ob[(size_t)(2 * tap + 1) * HW_ + px];
                float py = (float)(h - 1 + ky) + dy;
                float pxf = (float)(px - 1 + kx) + dx;
                float y0f = floorf(py), x0f = floorf(pxf);
                float ly = py - y0f, lx = pxf - x0f;
                int y0 = (int)y0f, x0 = (int)x0f;
                int y1 = y0 + 1,   x1 = x0 + 1;
                bool vy0 = (y0 >= 0) && (y0 < H_), vy1 = (y1 >= 0) && (y1 < H_);
                bool vx0 = (x0 >= 0) && (x0 < W_), vx1 = (x1 >= 0) && (x1 < W_);
                float4 wg;
                wg.x = (1.f - ly) * (1.f - lx) * ((vy0 && vx0) ? 1.f : 0.f);
                wg.y = (1.f - ly) * lx         * ((vy0 && vx1) ? 1.f : 0.f);
                wg.z = ly * (1.f - lx)         * ((vy1 && vx0) ? 1.f : 0.f);
                wg.w = ly * lx                 * ((vy1 && vx1) ? 1.f : 0.f);
                int y0c = min(max(y0, 0), H_ - 1), y1c = min(max(y1, 0), H_ - 1);
                int x0c = min(max(x0, 0), W_ - 1), x1c = min(max(x1, 0), W_ - 1);
                int4 ix;
                ix.x = y0c * W_ + x0c; ix.y = y0c * W_ + x1c;
                ix.z = y1c * W_ + x0c; ix.w = y1c * W_ + x1c;
                pwb[prv * 128 + px] = wg;
                pib[prv * 128 + px] = ix;
            }
        }

        // ---- interleaved gather(it) + mma(it-1) ----
#pragma unroll
        for (int i = 0; i < 8; ++i) {
            if (it < 9) {
                int px = i * 16 + (wid << 1) + half;
                float4 wg = pwb[cur * 128 + px];
                int4   ix = pib[cur * 128 + px];
                ulonglong2 a4 = *(const ulonglong2*)(xt + (size_t)ix.x * C_ + cs);
                ulonglong2 b4 = *(const ulonglong2*)(xt + (size_t)ix.y * C_ + cs);
                ulonglong2 c4 = *(const ulonglong2*)(xt + (size_t)ix.z * C_ + cs);
                ulonglong2 d4 = *(const ulonglong2*)(xt + (size_t)ix.w * C_ + cs);
                unsigned long long w00p = pk2(wg.x, wg.x);
                unsigned long long w01p = pk2(wg.y, wg.y);
                unsigned long long w10p = pk2(wg.z, wg.z);
                unsigned long long w11p = pk2(wg.w, wg.w);
                unsigned long long lo = fma2(w00p, a4.x,
                                        fma2(w01p, b4.x,
                                        fma2(w10p, c4.x,
                                        fma2(w11p, d4.x, 0ULL))));
                unsigned long long hi = fma2(w00p, a4.y,
                                        fma2(w01p, b4.y,
                                        fma2(w10p, c4.y,
                                        fma2(w11p, d4.y, 0ULL))));
                float2 flo = upk(lo), fhi = upk(hi);
                uint4 u;
                u.x = to_tf32(flo.x); u.y = to_tf32(flo.y);
                u.z = to_tf32(fhi.x); u.w = to_tf32(fhi.y);
                *(uint4*)(vcur + px * VP + cs) = u;
            }
            if (it > 0) {
                int k0 = i * 8;
                uint32_t a[2][4];
#pragma unroll
                for (int mt = 0; mt < 2; ++mt) {
                    int row = warp_m + mt * 16;
                    a[mt][0] = vprv[(row + g)     * VP + k0 + tg];
                    a[mt][1] = vprv[(row + g + 8) * VP + k0 + tg];
                    a[mt][2] = vprv[(row + g)     * VP + k0 + tg + 4];
                    a[mt][3] = vprv[(row + g + 8) * VP + k0 + tg + 4];
                }
                const uint32_t* wp2 = wprv + (i * 4 + tg) * 136 + warp_n * 2 + g * 2;
#pragma unroll
                for (int nb = 0; nb < 4; ++nb) {
                    uint2 bp = *(const uint2*)(wp2 + nb * 16);
#pragma unroll
                    for (int mt = 0; mt < 2; ++mt)
                        mma_tf32(acc[mt][nb], a[mt][0], a[mt][1], a[mt][2],
                                 a[mt][3], bp.x, bp.y);
                }
            }
        }
        __syncthreads();
    }

    // ---- epilogue: smem-transposed coalesced stores ----
    {
        uint32_t* outs = dsm;   // reuse: 64*132 = 8448 words
#pragma unroll
        for (int mt = 0; mt < 2; ++mt) {
            int p = warp_m + mt * 16 + g;
#pragma unroll
            for (int nb = 0; nb < 4; ++nb) {
                int o = warp_n + nb * 8 + tg * 2;
                outs[o       * 132 + p]     = __float_as_uint(acc[mt][nb][0]);
                outs[(o + 1) * 132 + p]     = __float_as_uint(acc[mt][nb][1]);
                outs[o       * 132 + p + 8] = __float_as_uint(acc[mt][nb][2]);
                outs[(o + 1) * 132 + p + 8] = __float_as_uint(acc[mt][nb][3]);
            }
        }
        __syncthreads();
        float* outb = out + ((size_t)b * COUT_ * H_ + h) * W_;
#pragma unroll
        for (int i = 0; i < 8; ++i) {
            int e = t + i * 256;
            int o = e >> 5, q = (e & 31) << 2;
            uint4 v = *(uint4*)(outs + o * 132 + q);
            *(uint4*)(outb + (size_t)o * HW_ + q) = v;
        }
    }
}

// ---------------------------------------------------------------------------
extern "C" void kernel_launch(void* const* d_in, const int* in_sizes, int n_in,
                              void* d_out, int out_size) {
    const float* x        = (const float*)d_in[0];
    const float* w_offset = (const float*)d_in[1];
    const float* w_deform = (const float*)d_in[2];
    float* out = (float*)d_out;

    cudaFuncSetAttribute(k_deform_mma,
                         cudaFuncAttributeMaxDynamicSharedMemorySize, DSM_BYTES);
    cudaFuncSetAttribute(k_offset_mma,
                         cudaFuncAttributeMaxDynamicSharedMemorySize, OSM_WORDS * 4);

    k_prep<<<710, 256>>>(x, w_deform, w_offset);
    k_offset_mma<<<B_ * H_, 256, OSM_WORDS * 4>>>();
    k_deform_mma<<<B_ * H_, 256, DSM_BYTES>>>(out);
}